// round 3
// baseline (speedup 1.0000x reference)
#include <cuda_runtime.h>
#include <cstdint>
#include <math.h>

#define T_DIM 8192
#define D_DIM 4096
#define E_DIM 64

// ---------------------------------------------------------------------------
// f32x2 packed helpers (Blackwell packed fp32 pipe: 2 FMA per inst at rt=2)
// ---------------------------------------------------------------------------
__device__ __forceinline__ unsigned long long pack2(float lo, float hi) {
    unsigned long long r;
    asm("mov.b64 %0, {%1,%2};" : "=l"(r) : "f"(lo), "f"(hi));
    return r;
}
__device__ __forceinline__ float2 unpack2(unsigned long long v) {
    float2 r;
    asm("mov.b64 {%0,%1}, %2;" : "=f"(r.x), "=f"(r.y) : "l"(v));
    return r;
}
__device__ __forceinline__ void fma2(unsigned long long& d,
                                     unsigned long long a,
                                     unsigned long long b) {
    asm("fma.rn.f32x2 %0, %1, %2, %0;" : "+l"(d) : "l"(a), "l"(b));
}

// ---------------------------------------------------------------------------
// GEMM: logits[T,64] = h[T,4096] @ W[64,4096]^T + bias
// BM=64, BN=64, BK=32, 256 threads, 4x4 micro-tile, f32x2 accumulation.
// Smem tiles stored transposed [BK][BM] with XOR swizzle (conflict-free).
// ---------------------------------------------------------------------------
__global__ __launch_bounds__(256, 1) void gemm64_kernel(
    const float* __restrict__ A,     // h [T, D]
    const float* __restrict__ B,     // W [E=64, D]
    const float* __restrict__ bias,  // [64]
    float* __restrict__ C)           // logits [T, 64]
{
    __shared__ __align__(16) float As[32 * 64];
    __shared__ __align__(16) float Bs[32 * 64];

    const int tid = threadIdx.x;
    const int tx  = tid & 15;   // col group (4 cols)
    const int ty  = tid >> 4;   // row group (4 rows)
    const int bm  = blockIdx.x * 64;

    // Global->smem load slots: 512 float4 per tile per matrix, 2 per thread.
    const int s0 = tid, s1 = tid + 256;
    const int r0 = s0 >> 3, q0 = s0 & 7;   // row in tile, float4-chunk in BK
    const int r1 = s1 >> 3, q1 = s1 & 7;

    const float4* A0 = (const float4*)(A + (size_t)(bm + r0) * D_DIM) + q0;
    const float4* A1 = (const float4*)(A + (size_t)(bm + r1) * D_DIM) + q1;
    const float4* B0 = (const float4*)(B + (size_t)r0 * D_DIM) + q0;
    const float4* B1 = (const float4*)(B + (size_t)r1 * D_DIM) + q1;

    // Swizzled physical column for the transposed store: pm = row ^ (4*kq)
    const int pm0 = r0 ^ (q0 << 2);
    const int pm1 = r1 ^ (q1 << 2);

    unsigned long long acc[4][2];
#pragma unroll
    for (int i = 0; i < 4; i++) { acc[i][0] = 0ull; acc[i][1] = 0ull; }

    // Prefetch tile 0
    float4 a0 = A0[0], a1 = A1[0], b0 = B0[0], b1 = B1[0];

    const int NT = D_DIM / 32;
    for (int kt = 0; kt < NT; kt++) {
        // Store current tile (smem is free: sync at end of previous iter)
        As[(q0 * 4 + 0) * 64 + pm0] = a0.x;
        As[(q0 * 4 + 1) * 64 + pm0] = a0.y;
        As[(q0 * 4 + 2) * 64 + pm0] = a0.z;
        As[(q0 * 4 + 3) * 64 + pm0] = a0.w;
        As[(q1 * 4 + 0) * 64 + pm1] = a1.x;
        As[(q1 * 4 + 1) * 64 + pm1] = a1.y;
        As[(q1 * 4 + 2) * 64 + pm1] = a1.z;
        As[(q1 * 4 + 3) * 64 + pm1] = a1.w;
        Bs[(q0 * 4 + 0) * 64 + pm0] = b0.x;
        Bs[(q0 * 4 + 1) * 64 + pm0] = b0.y;
        Bs[(q0 * 4 + 2) * 64 + pm0] = b0.z;
        Bs[(q0 * 4 + 3) * 64 + pm0] = b0.w;
        Bs[(q1 * 4 + 0) * 64 + pm1] = b1.x;
        Bs[(q1 * 4 + 1) * 64 + pm1] = b1.y;
        Bs[(q1 * 4 + 2) * 64 + pm1] = b1.z;
        Bs[(q1 * 4 + 3) * 64 + pm1] = b1.w;
        __syncthreads();

        // Prefetch next tile (overlaps DRAM latency with compute below)
        if (kt + 1 < NT) {
            const int off = (kt + 1) * 8;
            a0 = A0[off]; a1 = A1[off]; b0 = B0[off]; b1 = B1[off];
        }

#pragma unroll
        for (int k = 0; k < 32; k++) {
            const int sw = (k >> 2) << 2;
            float4 av = *(const float4*)&As[k * 64 + ((ty * 4) ^ sw)];
            ulonglong2 bv = *(const ulonglong2*)&Bs[k * 64 + ((tx * 4) ^ sw)];
            unsigned long long ax = pack2(av.x, av.x);
            unsigned long long ay = pack2(av.y, av.y);
            unsigned long long az = pack2(av.z, av.z);
            unsigned long long aw = pack2(av.w, av.w);
            fma2(acc[0][0], ax, bv.x); fma2(acc[0][1], ax, bv.y);
            fma2(acc[1][0], ay, bv.x); fma2(acc[1][1], ay, bv.y);
            fma2(acc[2][0], az, bv.x); fma2(acc[2][1], az, bv.y);
            fma2(acc[3][0], aw, bv.x); fma2(acc[3][1], aw, bv.y);
        }
        __syncthreads();
    }

    // Epilogue: add bias, store logits
    float4 bvec = *(const float4*)(bias + tx * 4);
#pragma unroll
    for (int i = 0; i < 4; i++) {
        float2 p0 = unpack2(acc[i][0]);
        float2 p1 = unpack2(acc[i][1]);
        float4 o;
        o.x = p0.x + bvec.x;
        o.y = p0.y + bvec.y;
        o.z = p1.x + bvec.z;
        o.w = p1.y + bvec.w;
        *(float4*)(C + (size_t)(bm + ty * 4 + i) * 64 + tx * 4) = o;
    }
}

// ---------------------------------------------------------------------------
// JAX threefry2x32, key = threefry_seed(42) = (0, 42)
// ---------------------------------------------------------------------------
__device__ __forceinline__ uint32_t rotl32(uint32_t x, int d) {
    return (x << d) | (x >> (32 - d));
}

__device__ __forceinline__ void threefry2x32(uint32_t x0, uint32_t x1,
                                             uint32_t& o0, uint32_t& o1) {
    const uint32_t k0 = 0u;
    const uint32_t k1 = 42u;
    const uint32_t k2 = 0u ^ 42u ^ 0x1BD11BDAu;
    x0 += k0; x1 += k1;
#define TF_RND(r) { x0 += x1; x1 = rotl32(x1, (r)); x1 ^= x0; }
    TF_RND(13) TF_RND(15) TF_RND(26) TF_RND(6)
    x0 += k1; x1 += k2 + 1u;
    TF_RND(17) TF_RND(29) TF_RND(16) TF_RND(24)
    x0 += k2; x1 += k0 + 2u;
    TF_RND(13) TF_RND(15) TF_RND(26) TF_RND(6)
    x0 += k0; x1 += k1 + 3u;
    TF_RND(17) TF_RND(29) TF_RND(16) TF_RND(24)
    x0 += k1; x1 += k2 + 4u;
    TF_RND(13) TF_RND(15) TF_RND(26) TF_RND(6)
    x0 += k2; x1 += k0 + 5u;
#undef TF_RND
    o0 = x0; o1 = x1;
}

// jax.random.uniform bit->float path: [1,2) mantissa trick, then affine + clamp
__device__ __forceinline__ float bits_to_unif(uint32_t bits) {
    float f = __uint_as_float((bits >> 9) | 0x3F800000u) - 1.0f;
    const float minv = 1e-6f;
    const float maxv = 1.0f - 1e-6f;
    float v = __fadd_rn(__fmul_rn(f, maxv - minv), minv);  // no FMA contraction
    return fmaxf(minv, v);
}

// ---------------------------------------------------------------------------
// Router: softmax weights from logits; Gumbel top-k mask.
//
// JAX >= 0.4.36 defaults jax_threefry_partitionable=True: random_bits for a
// size-n (<2^32) array computes, per flat index j,
//   (o0, o1) = threefry2x32(key, (hi=0, lo=j));   bits[j] = o0 ^ o1
// (NOT the legacy split-halves pairing).
// One block = 2 rows x 64 experts = 128 threads.
// ---------------------------------------------------------------------------
__global__ __launch_bounds__(128) void router64_kernel(
    const float* __restrict__ logits,
    const int* __restrict__ kptr,
    float* __restrict__ out_mask,
    float* __restrict__ out_weight)
{
    const int e   = threadIdx.x & 63;       // expert 0..63
    const int sub = threadIdx.x >> 6;       // row within block (0,1)
    const int row = blockIdx.x * 2 + sub;
    const int k   = kptr ? *kptr : 8;

    const uint32_t j = (uint32_t)(row * 64 + e);
    const float l = logits[j];

    uint32_t o0, o1;
    threefry2x32(0u, j, o0, o1);            // partitionable: counter (0, j)
    const uint32_t bits = o0 ^ o1;

    const float g = -logf(-logf(bits_to_unif(bits)));
    const float s = l + g;

    __shared__ float L[2][64], S[2][64];
    L[sub][e] = l; S[sub][e] = s;
    __syncthreads();

    // softmax (max-subtracted, matching jax.nn.softmax)
    float m = -3.402823466e+38f;
#pragma unroll
    for (int i = 0; i < 64; i++) m = fmaxf(m, L[sub][i]);
    float z = 0.f;
#pragma unroll
    for (int i = 0; i < 64; i++) z += expf(L[sub][i] - m);
    const float w = expf(l - m) / z;

    // top-k by rank count; ties -> lower index wins (lax.top_k stability)
    int c = 0;
#pragma unroll
    for (int i = 0; i < 64; i++) {
        const float v = S[sub][i];
        c += (v > s) || (v == s && i < e);
    }

    out_mask[j]   = (c < k) ? 1.0f : 0.0f;
    out_weight[j] = w;
}

// ---------------------------------------------------------------------------
// Output layout: tuple (mask, weight, logits) concatenated as f32.
// ---------------------------------------------------------------------------
extern "C" void kernel_launch(void* const* d_in, const int* in_sizes, int n_in,
                              void* d_out, int out_size) {
    const float* h    = (const float*)d_in[0];
    const float* W    = (const float*)d_in[1];
    const float* bias = (const float*)d_in[2];
    const int*   kptr = (n_in > 3) ? (const int*)d_in[3] : nullptr;

    float* out        = (float*)d_out;
    float* out_mask   = out;
    float* out_weight = out + (size_t)T_DIM * E_DIM;
    float* out_logits = out + 2 * (size_t)T_DIM * E_DIM;

    gemm64_kernel<<<T_DIM / 64, 256>>>(h, W, bias, out_logits);
    router64_kernel<<<T_DIM / 2, 128>>>(out_logits, kptr, out_mask, out_weight);
}